// round 6
// baseline (speedup 1.0000x reference)
#include <cuda_runtime.h>
#include <math.h>

#define SLEN 1024
#define NM   32
#define HID  128
#define NB   1024

typedef unsigned long long u64;

// ---------------- scratch (static device memory; no allocation) ----------------
__device__ float g_tabC[SLEN*NM];          // cos(2*pi*m*s/S), [s][m]
__device__ float g_tabS[SLEN*NM];          // sin(2*pi*m*s/S), [s][m]
__device__ float g_w1tr[NM*HID];           // [m][ch]
__device__ float g_w1ti[NM*HID];
__device__ float g_w2tr[NM*HID*HID];       // [m][i][o]
__device__ float g_w2ti[NM*HID*HID];
__device__ float g_Zf [2*NM*NB*HID];       // [(m*2+ri)][b][ch]
__device__ float g_of2[2*NM*NB*HID];       // [(m*2+ri)][b][o]

// ---------------- packed f32x2 helpers (sm_100+ FFMA2 path) ----------------
__device__ __forceinline__ u64 pk2(float lo, float hi) {
    u64 r; asm("mov.b64 %0, {%1, %2};" : "=l"(r) : "f"(lo), "f"(hi)); return r;
}
__device__ __forceinline__ void un2(u64 v, float& lo, float& hi) {
    asm("mov.b64 {%0, %1}, %2;" : "=f"(lo), "=f"(hi) : "l"(v));
}
__device__ __forceinline__ u64 f2fma(u64 a, u64 b, u64 c) {
    u64 d; asm("fma.rn.f32x2 %0, %1, %2, %3;" : "=l"(d) : "l"(a), "l"(b), "l"(c)); return d;
}
__device__ __forceinline__ u64 f2mul(u64 a, u64 b) {
    u64 d; asm("mul.rn.f32x2 %0, %1, %2;" : "=l"(d) : "l"(a), "l"(b)); return d;
}
__device__ __forceinline__ u64 dal(double d) { return __double_as_longlong(d); }
#define PKC(x) pk2((x), (x))

// Fast exact-enough GELU (A&S 7.1.26 erf, max abs err 1.5e-7), scalar form.
__device__ __forceinline__ float gelu_fast(float x) {
    float q    = fabsf(x) * 0.70710678118654752f;
    float t    = __fdividef(1.0f, fmaf(0.3275911f, q, 1.0f));
    float poly = fmaf(fmaf(fmaf(fmaf(1.061405429f, t, -1.453152027f),
                               t, 1.421413741f),
                          t, -0.284496736f),
                      t, 0.254829592f) * t;
    float er   = 1.0f - poly * __expf(-q * q);
    float phi  = fmaf(copysignf(er, x), 0.5f, 0.5f);
    return x * phi;
}

// Two-point GELU with packed polynomial.
__device__ __forceinline__ void gelu2(float xa, float xb, float& za, float& zb) {
    float qa = fabsf(xa) * 0.70710678118654752f;
    float qb = fabsf(xb) * 0.70710678118654752f;
    float ta = __fdividef(1.0f, fmaf(0.3275911f, qa, 1.0f));
    float tb = __fdividef(1.0f, fmaf(0.3275911f, qb, 1.0f));
    u64 t2 = pk2(ta, tb);
    u64 p  = f2fma(t2, PKC(1.061405429f), PKC(-1.453152027f));
    p = f2fma(p, t2, PKC(1.421413741f));
    p = f2fma(p, t2, PKC(-0.284496736f));
    p = f2fma(p, t2, PKC(0.254829592f));
    p = f2mul(p, t2);
    float ea = __expf(-qa * qa), eb = __expf(-qb * qb);
    float pa, pb; un2(p, pa, pb);
    float era = fmaf(-pa, ea, 1.0f), erb = fmaf(-pb, eb, 1.0f);
    za = xa * fmaf(copysignf(era, xa), 0.5f, 0.5f);
    zb = xb * fmaf(copysignf(erb, xb), 0.5f, 0.5f);
}

// ---------------- K_tab: exact trig tables ----------------
__global__ void k_tab() {
    int idx = blockIdx.x * blockDim.x + threadIdx.x;
    if (idx >= SLEN * NM) return;
    int s = idx >> 5, m = idx & 31;
    int k = (s * m) & (SLEN - 1);              // exact phase reduction
    float x = (float)k * (1.0f / 512.0f);      // angle = pi * x = 2*pi*k/1024
    float sv, cv;
    sincospif(x, &sv, &cv);
    g_tabC[idx] = cv;
    g_tabS[idx] = sv;
}

// ---------------- K_w: weight transposes ----------------
__global__ void k_w(const float* __restrict__ w1r, const float* __restrict__ w1i,
                    const float* __restrict__ w2r, const float* __restrict__ w2i) {
    int tid = blockIdx.x * blockDim.x + threadIdx.x;
    if (tid < NM * HID) {                      // w1 src: [ch][m]
        int ch = tid >> 5, m = tid & 31;
        g_w1tr[m * HID + ch] = w1r[tid];
        g_w1ti[m * HID + ch] = w1i[tid];
    }
    if (tid < NM * HID * HID) {                // w2 src: [i][o][m]
        int m = tid & 31; int io = tid >> 5;
        int i = io >> 7;  int o = io & 127;
        g_w2tr[(m * HID + i) * HID + o] = w2r[tid];
        g_w2ti[(m * HID + i) * HID + o] = w2i[tid];
    }
}

// ---------------- K_layer1: DFT(h) -> mix w1 -> synth+gelu+analyze (fused, f32x2) -------
// Block = one batch row b. 256 threads.
// Warp w handles channels [16w, 16w+16); lane>>4 selects mode-half (16 modes each).
// Quarter-wave symmetry: iteration p covers spatial points {p, 1024-p, 512+p, 512-p}.
__global__ __launch_bounds__(256, 2) void k_layer1(const float* __restrict__ hin) {
    __shared__ float h_sm[SLEN];
    __shared__ float red[64 * 4];
    __shared__ float Hf[64];                   // [0:32) real, [32:64) imag
    int b = blockIdx.x;
    int t = threadIdx.x;

    // stage h row
    {
        const float4* src = reinterpret_cast<const float4*>(hin + (size_t)b * SLEN);
        float4* dst = reinterpret_cast<float4*>(h_sm);
        for (int j = t; j < SLEN / 4; j += 256) dst[j] = src[j];
    }
    __syncthreads();

    // forward DFT of h: Hfr[m] = sum h*cos, Hfi[m] = -sum h*sin
    {
        int out = t & 63, seg = t >> 6;
        int m = out & 31; int isI = out >> 5;
        const float* tab = isI ? g_tabS : g_tabC;
        float acc = 0.0f;
        int s0 = seg * 256;
        #pragma unroll 8
        for (int j = 0; j < 256; j++) {
            int s = s0 + j;
            acc = fmaf(h_sm[s], __ldg(&tab[s * NM + m]), acc);
        }
        red[out * 4 + seg] = acc;
    }
    __syncthreads();
    if (t < 64) {
        float v = red[t * 4] + red[t * 4 + 1] + red[t * 4 + 2] + red[t * 4 + 3];
        Hf[t] = (t >= 32) ? -v : v;
    }
    __syncthreads();

    int lane = t & 31;
    int w    = t >> 5;
    int hh   = lane >> 4;                      // mode-half
    int ch   = w * 16 + (lane & 15);
    float sgn = hh ? -1.0f : 1.0f;             // parity fold sign

    // synthesis coefficients: y(s) = sum ar[m]*cos + ai[m]*sin
    float ar[16], ai[16], zfr[16], zfi[16];
    #pragma unroll
    for (int j = 0; j < 16; j++) {
        int m = hh * 16 + j;
        float hr = Hf[m], hi = Hf[32 + m];
        float a1 = __ldg(&g_w1tr[m * HID + ch]);
        float b1 = __ldg(&g_w1ti[m * HID + ch]);
        float km = (m == 0) ? (1.0f / SLEN) : (2.0f / SLEN);
        ar[j] = km * (hr * a1 - hi * b1);
        float oi = km * (hr * b1 + hi * a1);
        ai[j] = (m == 0) ? 0.0f : -oi;         // DC imag dropped by irfft
        zfr[j] = 0.0f; zfi[j] = 0.0f;
    }

    const float4* tC = reinterpret_cast<const float4*>(g_tabC);
    const float4* tS = reinterpret_cast<const float4*>(g_tabS);
    int base = hh * 4;                         // float4 offset inside 8-float4 row

    // special points s=0 and s=512 (sin == 0 there)
    {
        float c0[16], c5[16];
        #pragma unroll
        for (int q = 0; q < 4; q++) {
            float4 a = __ldg(&tC[0 * 8 + base + q]);
            float4 c = __ldg(&tC[512 * 8 + base + q]);
            c0[4*q+0]=a.x; c0[4*q+1]=a.y; c0[4*q+2]=a.z; c0[4*q+3]=a.w;
            c5[4*q+0]=c.x; c5[4*q+1]=c.y; c5[4*q+2]=c.z; c5[4*q+3]=c.w;
        }
        float u0 = 0.0f, u5 = 0.0f;
        #pragma unroll
        for (int j = 0; j < 16; j++) {
            u0 = fmaf(ar[j], c0[j], u0);
            u5 = fmaf(ar[j], c5[j], u5);
        }
        u0 += __shfl_xor_sync(0xffffffffu, u0, 16);
        u5 += __shfl_xor_sync(0xffffffffu, u5, 16);
        float z0 = gelu_fast(u0), z5 = gelu_fast(u5);
        #pragma unroll
        for (int j = 0; j < 16; j++)
            zfr[j] = fmaf(z0, c0[j], fmaf(z5, c5[j], zfr[j]));
    }

    // special pair s=256 / s=768 (half-wave symmetry)
    {
        float c[16], sn[16];
        #pragma unroll
        for (int q = 0; q < 4; q++) {
            float4 a = __ldg(&tC[256 * 8 + base + q]);
            float4 s = __ldg(&tS[256 * 8 + base + q]);
            c [4*q+0]=a.x; c [4*q+1]=a.y; c [4*q+2]=a.z; c [4*q+3]=a.w;
            sn[4*q+0]=s.x; sn[4*q+1]=s.y; sn[4*q+2]=s.z; sn[4*q+3]=s.w;
        }
        float u = 0.0f, v = 0.0f;
        #pragma unroll
        for (int j = 0; j < 16; j++) {
            u = fmaf(ar[j], c[j], u);
            v = fmaf(ai[j], sn[j], v);
        }
        float ya = u + v, yb = u - v;          // y(256), y(768)
        ya += __shfl_xor_sync(0xffffffffu, ya, 16);
        yb += __shfl_xor_sync(0xffffffffu, yb, 16);
        float ymine = hh ? yb : ya;
        float zmine = gelu_fast(ymine);
        float zoth  = __shfl_xor_sync(0xffffffffu, zmine, 16);
        float z0 = hh ? zoth : zmine;          // z(256)
        float z1 = hh ? zmine : zoth;          // z(768)
        float zp = z0 + z1, zd = z1 - z0;
        #pragma unroll
        for (int j = 0; j < 16; j++) {
            zfr[j] = fmaf(zp, c[j],  zfr[j]);
            zfi[j] = fmaf(zd, sn[j], zfi[j]);
        }
    }

    // pack coefficients and accumulators into f32x2 pairs (even/odd mode lanes)
    u64 ar2[8], ai2[8], zfr2[8], zfi2[8];
    #pragma unroll
    for (int k = 0; k < 8; k++) {
        ar2[k]  = pk2(ar[2*k],  ar[2*k+1]);
        ai2[k]  = pk2(ai[2*k],  ai[2*k+1]);
        zfr2[k] = pk2(zfr[2*k], zfr[2*k+1]);
        zfi2[k] = pk2(zfi[2*k], zfi[2*k+1]);
    }

    const double2* tC2 = reinterpret_cast<const double2*>(g_tabC);
    const double2* tS2 = reinterpret_cast<const double2*>(g_tabS);
    int base2 = hh * 2;                        // double2 offset within 8-double2 row... (row=8 d2)

    // quad points {p, 1024-p, 512+p, 512-p}, p = 1..255  (packed FFMA2 core)
    for (int p = 1; p <= 255; p++) {
        u64 c2[8], s2[8];
        #pragma unroll
        for (int q = 0; q < 2; q++) {
            double2 a = __ldg(&tC2[p * 4 + base2 + q]);
            double2 s = __ldg(&tS2[p * 4 + base2 + q]);
            c2[4*q+0] = dal(a.x); c2[4*q+1] = dal(a.y);
            s2[4*q+0] = dal(s.x); s2[4*q+1] = dal(s.y);
        }
        // note: row = 32 floats = 4 double2? (32 floats = 16 doubles = 8 double2)
        #pragma unroll
        for (int q = 0; q < 2; q++) {
            double2 a = __ldg(&tC2[p * 8 + hh * 4 + 2 + q]);
            (void)a;
        }
        // (corrected full loads below)
        #pragma unroll
        for (int q = 0; q < 4; q++) {
            double2 a = __ldg(&tC2[p * 8 + hh * 4 + q]);
            double2 s = __ldg(&tS2[p * 8 + hh * 4 + q]);
            c2[2*q+0] = dal(a.x); c2[2*q+1] = dal(a.y);
            s2[2*q+0] = dal(s.x); s2[2*q+1] = dal(s.y);
        }

        u64 u2 = 0ull, v2 = 0ull;              // (even, odd) partial sums
        #pragma unroll
        for (int k = 0; k < 8; k++) {
            u2 = f2fma(ar2[k], c2[k], u2);
            v2 = f2fma(ai2[k], s2[k], v2);
        }
        float ue, uo, ve, vo;
        un2(u2, ue, uo); un2(v2, ve, vo);
        ue += __shfl_xor_sync(0xffffffffu, ue, 16);
        uo += __shfl_xor_sync(0xffffffffu, uo, 16);
        ve += __shfl_xor_sync(0xffffffffu, ve, 16);
        vo += __shfl_xor_sync(0xffffffffu, vo, 16);
        float U = fmaf(sgn, uo, ue);
        float V = fmaf(sgn, vo, ve);
        float ya = U + V, yb = U - V;
        float za, zb;
        gelu2(ya, yb, za, zb);
        float sP = za + zb;
        float sM = zb - za;
        float oP = __shfl_xor_sync(0xffffffffu, sP, 16);
        float oM = __shfl_xor_sync(0xffffffffu, sM, 16);
        float A = hh ? oP : sP,  B = hh ? sP : oP;
        float C = hh ? oM : sM,  D = hh ? sM : oM;
        u64 r2 = pk2(A + B, A - B);            // (rp, rm)
        u64 i2 = pk2(C + D, C - D);            // (ip, im)
        #pragma unroll
        for (int k = 0; k < 8; k++) {
            zfr2[k] = f2fma(r2, c2[k], zfr2[k]);
            zfi2[k] = f2fma(i2, s2[k], zfi2[k]);
        }
    }

    #pragma unroll
    for (int k = 0; k < 8; k++) {
        float r0, r1, i0, i1;
        un2(zfr2[k], r0, r1);
        un2(zfi2[k], i0, i1);
        int m0 = hh * 16 + 2 * k;
        g_Zf[((size_t)((m0    ) * 2 + 0) * NB + b) * HID + ch] = r0;
        g_Zf[((size_t)((m0    ) * 2 + 1) * NB + b) * HID + ch] = i0;
        g_Zf[((size_t)((m0 + 1) * 2 + 0) * NB + b) * HID + ch] = r1;
        g_Zf[((size_t)((m0 + 1) * 2 + 1) * NB + b) * HID + ch] = i1;
    }
}

// ---------------- K_mix: per-mode complex GEMM, packed f32x2 complex MAC ----------------
// acc(re,im) += (zr,zr)*(wr,wi) + (zi,zi)*(-wi,wr)
__global__ __launch_bounds__(256, 2) void k_mix() {
    int m  = blockIdx.x;                       // mode
    int bt = blockIdx.y;                       // b-tile of 64
    __shared__ float  Zr[64 * 17], Zi[64 * 17];
    __shared__ float2 Wp[16 * 128];            // (wr, wi)
    __shared__ float2 Wn[16 * 128];            // (-wi, wr)
    int t = threadIdx.x;
    int bo_g = t >> 4, o_g = t & 15;
    int b0 = bo_g * 4, o0 = o_g * 8;

    u64 acc2[4][8];
    #pragma unroll
    for (int x = 0; x < 4; x++)
        #pragma unroll
        for (int y = 0; y < 8; y++) acc2[x][y] = 0ull;

    const float* Zsr = g_Zf + ((size_t)(m * 2 + 0) * NB + bt * 64) * HID;
    const float* Zsi = g_Zf + ((size_t)(m * 2 + 1) * NB + bt * 64) * HID;

    for (int i0 = 0; i0 < HID; i0 += 16) {
        __syncthreads();
        for (int idx = t; idx < 64 * 16; idx += 256) {
            int bb = idx >> 4, ic = idx & 15;
            Zr[bb * 17 + ic] = Zsr[bb * HID + i0 + ic];
            Zi[bb * 17 + ic] = Zsi[bb * HID + i0 + ic];
        }
        for (int idx = t; idx < 16 * 128; idx += 256) {
            int ic = idx >> 7, o = idx & 127;
            float wr = g_w2tr[((size_t)m * HID + i0 + ic) * HID + o];
            float wi = g_w2ti[((size_t)m * HID + i0 + ic) * HID + o];
            Wp[idx] = make_float2(wr, wi);
            Wn[idx] = make_float2(-wi, wr);
        }
        __syncthreads();
        #pragma unroll 2
        for (int ic = 0; ic < 16; ic++) {
            u64 zrr[4], zii[4];
            #pragma unroll
            for (int bb = 0; bb < 4; bb++) {
                float zr = Zr[(b0 + bb) * 17 + ic];
                float zi = Zi[(b0 + bb) * 17 + ic];
                zrr[bb] = pk2(zr, zr);
                zii[bb] = pk2(zi, zi);
            }
            u64 wp[8], wn[8];
            const double2* wp2 = reinterpret_cast<const double2*>(&Wp[ic * 128 + o0]);
            const double2* wn2 = reinterpret_cast<const double2*>(&Wn[ic * 128 + o0]);
            #pragma unroll
            for (int q = 0; q < 4; q++) {
                double2 a = wp2[q];
                double2 c = wn2[q];
                wp[2*q+0] = dal(a.x); wp[2*q+1] = dal(a.y);
                wn[2*q+0] = dal(c.x); wn[2*q+1] = dal(c.y);
            }
            #pragma unroll
            for (int bb = 0; bb < 4; bb++)
                #pragma unroll
                for (int oo = 0; oo < 8; oo++) {
                    acc2[bb][oo] = f2fma(zrr[bb], wp[oo], acc2[bb][oo]);
                    acc2[bb][oo] = f2fma(zii[bb], wn[oo], acc2[bb][oo]);
                }
        }
    }
    #pragma unroll
    for (int bb = 0; bb < 4; bb++) {
        size_t rowr = ((size_t)(m * 2 + 0) * NB + bt * 64 + b0 + bb) * HID + o0;
        size_t rowi = ((size_t)(m * 2 + 1) * NB + bt * 64 + b0 + bb) * HID + o0;
        #pragma unroll
        for (int oo = 0; oo < 8; oo++) {
            float re, im;
            un2(acc2[bb][oo], re, im);
            g_of2[rowr + oo] = re;
            g_of2[rowi + oo] = im;
        }
    }
}

// ---------------- K_layer2: synth + gelu + mean (quad symmetry, f32x2) ----------------
__global__ __launch_bounds__(256, 2) void k_layer2(float* __restrict__ out) {
    int b = blockIdx.x;
    int t = threadIdx.x;
    int lane = t & 31, w = t >> 5, hh = lane >> 4;
    int o = w * 16 + (lane & 15);
    float sgn = hh ? -1.0f : 1.0f;

    float br[16], bi[16];
    #pragma unroll
    for (int j = 0; j < 16; j++) {
        int m = hh * 16 + j;
        float orr = __ldg(&g_of2[((size_t)(m * 2 + 0) * NB + b) * HID + o]);
        float oii = __ldg(&g_of2[((size_t)(m * 2 + 1) * NB + b) * HID + o]);
        float km = (m == 0) ? (1.0f / SLEN) : (2.0f / SLEN);
        br[j] = km * orr;
        bi[j] = (m == 0) ? 0.0f : -km * oii;
    }

    const float4* tC = reinterpret_cast<const float4*>(g_tabC);
    const float4* tS = reinterpret_cast<const float4*>(g_tabS);
    int base = hh * 4;
    float acc = 0.0f;                          // per-thread partial (own points only)

    {   // s=0 (t0 adds) and s=512 (t1 adds)
        float c0[16], c5[16];
        #pragma unroll
        for (int q = 0; q < 4; q++) {
            float4 a = __ldg(&tC[0 * 8 + base + q]);
            float4 c = __ldg(&tC[512 * 8 + base + q]);
            c0[4*q+0]=a.x; c0[4*q+1]=a.y; c0[4*q+2]=a.z; c0[4*q+3]=a.w;
            c5[4*q+0]=c.x; c5[4*q+1]=c.y; c5[4*q+2]=c.z; c5[4*q+3]=c.w;
        }
        float u0 = 0.0f, u5 = 0.0f;
        #pragma unroll
        for (int j = 0; j < 16; j++) {
            u0 = fmaf(br[j], c0[j], u0);
            u5 = fmaf(br[j], c5[j], u5);
        }
        u0 += __shfl_xor_sync(0xffffffffu, u0, 16);
        u5 += __shfl_xor_sync(0xffffffffu, u5, 16);
        acc += gelu_fast(hh ? u5 : u0);
    }

    {   // s=256 (t0 adds) / s=768 (t1 adds)
        float c[16], sn[16];
        #pragma unroll
        for (int q = 0; q < 4; q++) {
            float4 a = __ldg(&tC[256 * 8 + base + q]);
            float4 s = __ldg(&tS[256 * 8 + base + q]);
            c [4*q+0]=a.x; c [4*q+1]=a.y; c [4*q+2]=a.z; c [4*q+3]=a.w;
            sn[4*q+0]=s.x; sn[4*q+1]=s.y; sn[4*q+2]=s.z; sn[4*q+3]=s.w;
        }
        float u = 0.0f, v = 0.0f;
        #pragma unroll
        for (int j = 0; j < 16; j++) {
            u = fmaf(br[j], c[j], u);
            v = fmaf(bi[j], sn[j], v);
        }
        float ya = u + v, yb = u - v;
        ya += __shfl_xor_sync(0xffffffffu, ya, 16);
        yb += __shfl_xor_sync(0xffffffffu, yb, 16);
        acc += gelu_fast(hh ? yb : ya);
    }

    // pack
    u64 br2[8], bi2[8];
    #pragma unroll
    for (int k = 0; k < 8; k++) {
        br2[k] = pk2(br[2*k], br[2*k+1]);
        bi2[k] = pk2(bi[2*k], bi[2*k+1]);
    }

    const double2* tC2 = reinterpret_cast<const double2*>(g_tabC);
    const double2* tS2 = reinterpret_cast<const double2*>(g_tabS);

    for (int p = 1; p <= 255; p++) {
        u64 c2[8], s2[8];
        #pragma unroll
        for (int q = 0; q < 4; q++) {
            double2 a = __ldg(&tC2[p * 8 + hh * 4 + q]);
            double2 s = __ldg(&tS2[p * 8 + hh * 4 + q]);
            c2[2*q+0] = dal(a.x); c2[2*q+1] = dal(a.y);
            s2[2*q+0] = dal(s.x); s2[2*q+1] = dal(s.y);
        }
        u64 u2 = 0ull, v2 = 0ull;
        #pragma unroll
        for (int k = 0; k < 8; k++) {
            u2 = f2fma(br2[k], c2[k], u2);
            v2 = f2fma(bi2[k], s2[k], v2);
        }
        float ue, uo, ve, vo;
        un2(u2, ue, uo); un2(v2, ve, vo);
        ue += __shfl_xor_sync(0xffffffffu, ue, 16);
        uo += __shfl_xor_sync(0xffffffffu, uo, 16);
        ve += __shfl_xor_sync(0xffffffffu, ve, 16);
        vo += __shfl_xor_sync(0xffffffffu, vo, 16);
        float U = fmaf(sgn, uo, ue);
        float V = fmaf(sgn, vo, ve);
        float za, zb;
        gelu2(U + V, U - V, za, zb);
        acc += za + zb;
    }

    acc += __shfl_xor_sync(0xffffffffu, acc, 16);
    if (hh == 0) out[(size_t)b * HID + o] = acc * (1.0f / SLEN);
}

// ---------------- launch ----------------
extern "C" void kernel_launch(void* const* d_in, const int* in_sizes, int n_in,
                              void* d_out, int out_size) {
    // identify inputs by size (order within a size group preserved: r then i)
    const float* hin = nullptr;
    const float* w1p[2] = {nullptr, nullptr};
    const float* w2p[2] = {nullptr, nullptr};
    int n1 = 0, n2 = 0;
    for (int i = 0; i < n_in; i++) {
        int sz = in_sizes[i];
        const float* p = (const float*)d_in[i];
        if (sz == NB * SLEN) hin = p;
        else if (sz == HID * NM) { if (n1 < 2) w1p[n1++] = p; }
        else if (sz == HID * HID * NM) { if (n2 < 2) w2p[n2++] = p; }
    }
    float* out = (float*)d_out;

    k_tab<<<(SLEN * NM + 255) / 256, 256>>>();
    k_w<<<(NM * HID * HID + 255) / 256, 256>>>(w1p[0], w1p[1], w2p[0], w2p[1]);
    k_layer1<<<NB, 256>>>(hin);
    dim3 g3(NM, 16);
    k_mix<<<g3, 256>>>();
    k_layer2<<<NB, 256>>>(out);
}

// round 7
// speedup vs baseline: 1.2591x; 1.2591x over previous
#include <cuda_runtime.h>
#include <math.h>

#define SLEN 1024
#define NM   32
#define HID  128
#define NB   1024

typedef unsigned long long u64;

// ---------------- scratch (static device memory; no allocation) ----------------
__device__ float g_tabC[SLEN*NM];          // cos(2*pi*m*s/S), [s][m]
__device__ float g_tabS[SLEN*NM];          // sin(2*pi*m*s/S), [s][m]
__device__ float g_w1tr[NM*HID];           // [m][ch]
__device__ float g_w1ti[NM*HID];
__device__ float g_w2tr[NM*HID*HID];       // [m][i][o]
__device__ float g_w2ti[NM*HID*HID];
__device__ float g_Zf [2*NM*NB*HID];       // [(m*2+ri)][b][ch]
__device__ float g_of2[2*NM*NB*HID];       // [(m*2+ri)][b][o]

// ---------------- packed f32x2 helpers ----------------
__device__ __forceinline__ u64 pk2(float lo, float hi) {
    u64 r; asm("mov.b64 %0, {%1, %2};" : "=l"(r) : "f"(lo), "f"(hi)); return r;
}
__device__ __forceinline__ void un2(u64 v, float& lo, float& hi) {
    asm("mov.b64 {%0, %1}, %2;" : "=f"(lo), "=f"(hi) : "l"(v));
}
__device__ __forceinline__ u64 f2fma(u64 a, u64 b, u64 c) {
    u64 d; asm("fma.rn.f32x2 %0, %1, %2, %3;" : "=l"(d) : "l"(a), "l"(b), "l"(c)); return d;
}
__device__ __forceinline__ u64 f2mul(u64 a, u64 b) {
    u64 d; asm("mul.rn.f32x2 %0, %1, %2;" : "=l"(d) : "l"(a), "l"(b)); return d;
}
__device__ __forceinline__ u64 dal(double d) { return __double_as_longlong(d); }
#define PKC(x) pk2((x), (x))

// Fast exact-enough GELU (A&S 7.1.26 erf, max abs err 1.5e-7), scalar form.
__device__ __forceinline__ float gelu_fast(float x) {
    float q    = fabsf(x) * 0.70710678118654752f;
    float t    = __fdividef(1.0f, fmaf(0.3275911f, q, 1.0f));
    float poly = fmaf(fmaf(fmaf(fmaf(1.061405429f, t, -1.453152027f),
                               t, 1.421413741f),
                          t, -0.284496736f),
                      t, 0.254829592f) * t;
    float er   = 1.0f - poly * __expf(-q * q);
    float phi  = fmaf(copysignf(er, x), 0.5f, 0.5f);
    return x * phi;
}

// Two-point GELU with packed polynomial.
__device__ __forceinline__ void gelu2(float xa, float xb, float& za, float& zb) {
    float qa = fabsf(xa) * 0.70710678118654752f;
    float qb = fabsf(xb) * 0.70710678118654752f;
    float ta = __fdividef(1.0f, fmaf(0.3275911f, qa, 1.0f));
    float tb = __fdividef(1.0f, fmaf(0.3275911f, qb, 1.0f));
    u64 t2 = pk2(ta, tb);
    u64 p  = f2fma(t2, PKC(1.061405429f), PKC(-1.453152027f));
    p = f2fma(p, t2, PKC(1.421413741f));
    p = f2fma(p, t2, PKC(-0.284496736f));
    p = f2fma(p, t2, PKC(0.254829592f));
    p = f2mul(p, t2);
    float ea = __expf(-qa * qa), eb = __expf(-qb * qb);
    float pa, pb; un2(p, pa, pb);
    float era = fmaf(-pa, ea, 1.0f), erb = fmaf(-pb, eb, 1.0f);
    za = xa * fmaf(copysignf(era, xa), 0.5f, 0.5f);
    zb = xb * fmaf(copysignf(erb, xb), 0.5f, 0.5f);
}

// ---------------- K_tab: exact trig tables ----------------
__global__ void k_tab() {
    int idx = blockIdx.x * blockDim.x + threadIdx.x;
    if (idx >= SLEN * NM) return;
    int s = idx >> 5, m = idx & 31;
    int k = (s * m) & (SLEN - 1);              // exact phase reduction
    float x = (float)k * (1.0f / 512.0f);      // angle = pi * x = 2*pi*k/1024
    float sv, cv;
    sincospif(x, &sv, &cv);
    g_tabC[idx] = cv;
    g_tabS[idx] = sv;
}

// ---------------- K_w: weight transposes ----------------
__global__ void k_w(const float* __restrict__ w1r, const float* __restrict__ w1i,
                    const float* __restrict__ w2r, const float* __restrict__ w2i) {
    int tid = blockIdx.x * blockDim.x + threadIdx.x;
    if (tid < NM * HID) {                      // w1 src: [ch][m]
        int ch = tid >> 5, m = tid & 31;
        g_w1tr[m * HID + ch] = w1r[tid];
        g_w1ti[m * HID + ch] = w1i[tid];
    }
    if (tid < NM * HID * HID) {                // w2 src: [i][o][m]
        int m = tid & 31; int io = tid >> 5;
        int i = io >> 7;  int o = io & 127;
        g_w2tr[(m * HID + i) * HID + o] = w2r[tid];
        g_w2ti[(m * HID + i) * HID + o] = w2i[tid];
    }
}

// ---------------- K_layer1: DFT(h) -> mix w1 -> synth+gelu+analyze (fused, f32x2) -------
__global__ __launch_bounds__(256, 2) void k_layer1(const float* __restrict__ hin) {
    __shared__ float h_sm[SLEN];
    __shared__ float red[64 * 4];
    __shared__ float Hf[64];                   // [0:32) real, [32:64) imag
    int b = blockIdx.x;
    int t = threadIdx.x;

    // stage h row
    {
        const float4* src = reinterpret_cast<const float4*>(hin + (size_t)b * SLEN);
        float4* dst = reinterpret_cast<float4*>(h_sm);
        for (int j = t; j < SLEN / 4; j += 256) dst[j] = src[j];
    }
    __syncthreads();

    // forward DFT of h: Hfr[m] = sum h*cos, Hfi[m] = -sum h*sin
    {
        int out = t & 63, seg = t >> 6;
        int m = out & 31; int isI = out >> 5;
        const float* tab = isI ? g_tabS : g_tabC;
        float acc = 0.0f;
        int s0 = seg * 256;
        #pragma unroll 8
        for (int j = 0; j < 256; j++) {
            int s = s0 + j;
            acc = fmaf(h_sm[s], __ldg(&tab[s * NM + m]), acc);
        }
        red[out * 4 + seg] = acc;
    }
    __syncthreads();
    if (t < 64) {
        float v = red[t * 4] + red[t * 4 + 1] + red[t * 4 + 2] + red[t * 4 + 3];
        Hf[t] = (t >= 32) ? -v : v;
    }
    __syncthreads();

    int lane = t & 31;
    int w    = t >> 5;
    int hh   = lane >> 4;                      // mode-half / point-group owner
    int ch   = w * 16 + (lane & 15);

    // synthesis coefficients: y(s) = sum ar[m]*cos + ai[m]*sin
    float ar[16], ai[16], zfr[16], zfi[16];
    #pragma unroll
    for (int j = 0; j < 16; j++) {
        int m = hh * 16 + j;
        float hr = Hf[m], hi = Hf[32 + m];
        float a1 = __ldg(&g_w1tr[m * HID + ch]);
        float b1 = __ldg(&g_w1ti[m * HID + ch]);
        float km = (m == 0) ? (1.0f / SLEN) : (2.0f / SLEN);
        ar[j] = km * (hr * a1 - hi * b1);
        float oi = km * (hr * b1 + hi * a1);
        ai[j] = (m == 0) ? 0.0f : -oi;         // DC imag dropped by irfft
        zfr[j] = 0.0f; zfi[j] = 0.0f;
    }

    const float4* tC = reinterpret_cast<const float4*>(g_tabC);
    const float4* tS = reinterpret_cast<const float4*>(g_tabS);
    int base = hh * 4;                         // float4 offset inside 8-float4 row

    // special points s=0 and s=512 (sin == 0 there)
    {
        float c0[16], c5[16];
        #pragma unroll
        for (int q = 0; q < 4; q++) {
            float4 a = __ldg(&tC[0 * 8 + base + q]);
            float4 c = __ldg(&tC[512 * 8 + base + q]);
            c0[4*q+0]=a.x; c0[4*q+1]=a.y; c0[4*q+2]=a.z; c0[4*q+3]=a.w;
            c5[4*q+0]=c.x; c5[4*q+1]=c.y; c5[4*q+2]=c.z; c5[4*q+3]=c.w;
        }
        float u0 = 0.0f, u5 = 0.0f;
        #pragma unroll
        for (int j = 0; j < 16; j++) {
            u0 = fmaf(ar[j], c0[j], u0);
            u5 = fmaf(ar[j], c5[j], u5);
        }
        u0 += __shfl_xor_sync(0xffffffffu, u0, 16);
        u5 += __shfl_xor_sync(0xffffffffu, u5, 16);
        float z0 = gelu_fast(u0), z5 = gelu_fast(u5);
        #pragma unroll
        for (int j = 0; j < 16; j++)
            zfr[j] = fmaf(z0, c0[j], fmaf(z5, c5[j], zfr[j]));
    }

    // special pair s=256 / s=768 (half-wave symmetry)
    {
        float c[16], sn[16];
        #pragma unroll
        for (int q = 0; q < 4; q++) {
            float4 a = __ldg(&tC[256 * 8 + base + q]);
            float4 s = __ldg(&tS[256 * 8 + base + q]);
            c [4*q+0]=a.x; c [4*q+1]=a.y; c [4*q+2]=a.z; c [4*q+3]=a.w;
            sn[4*q+0]=s.x; sn[4*q+1]=s.y; sn[4*q+2]=s.z; sn[4*q+3]=s.w;
        }
        float u = 0.0f, v = 0.0f;
        #pragma unroll
        for (int j = 0; j < 16; j++) {
            u = fmaf(ar[j], c[j], u);
            v = fmaf(ai[j], sn[j], v);
        }
        float ya = u + v, yb = u - v;          // y(256), y(768)
        ya += __shfl_xor_sync(0xffffffffu, ya, 16);
        yb += __shfl_xor_sync(0xffffffffu, yb, 16);
        float ymine = hh ? yb : ya;
        float zmine = gelu_fast(ymine);
        float zoth  = __shfl_xor_sync(0xffffffffu, zmine, 16);
        float z0 = hh ? zoth : zmine;          // z(256)
        float z1 = hh ? zmine : zoth;          // z(768)
        float zp = z0 + z1, zd = z1 - z0;
        #pragma unroll
        for (int j = 0; j < 16; j++) {
            zfr[j] = fmaf(zp, c[j],  zfr[j]);
            zfi[j] = fmaf(zd, sn[j], zfi[j]);
        }
    }

    // pack coefficients and accumulators into f32x2 pairs (even/odd mode lanes)
    u64 ar2[8], ai2[8], zfr2[8], zfi2[8];
    #pragma unroll
    for (int k = 0; k < 8; k++) {
        ar2[k]  = pk2(ar[2*k],  ar[2*k+1]);
        ai2[k]  = pk2(ai[2*k],  ai[2*k+1]);
        zfr2[k] = pk2(zfr[2*k], zfr[2*k+1]);
        zfi2[k] = pk2(zfi[2*k], zfi[2*k+1]);
    }

    const double2* tC2 = reinterpret_cast<const double2*>(g_tabC);
    const double2* tS2 = reinterpret_cast<const double2*>(g_tabS);

    // quad points {p, 1024-p, 512+p, 512-p}, p = 1..255  (packed FFMA2 core)
    for (int p = 1; p <= 255; p++) {
        u64 c2[8], s2[8];
        #pragma unroll
        for (int q = 0; q < 4; q++) {
            double2 a = __ldg(&tC2[p * 8 + hh * 4 + q]);
            double2 s = __ldg(&tS2[p * 8 + hh * 4 + q]);
            c2[2*q+0] = dal(a.x); c2[2*q+1] = dal(a.y);
            s2[2*q+0] = dal(s.x); s2[2*q+1] = dal(s.y);
        }

        u64 u2 = 0ull, v2 = 0ull;              // (even, odd) partial sums
        #pragma unroll
        for (int k = 0; k < 8; k++) {
            u2 = f2fma(ar2[k], c2[k], u2);
            v2 = f2fma(ai2[k], s2[k], v2);
        }
        float ue, uo, ve, vo;
        un2(u2, ue, uo); un2(v2, ve, vo);
        // pre-fold parity combinations; one shuffle per quantity:
        // t0's points need Lp = ue+uo; t1's points need Lm = ue-uo (sum over both threads)
        float Lp = ue + uo, Lm = ue - uo;
        float Mp = ve + vo, Mm = ve - vo;
        float keepU = hh ? Lm : Lp, sendU = hh ? Lp : Lm;
        float keepV = hh ? Mm : Mp, sendV = hh ? Mp : Mm;
        float U = keepU + __shfl_xor_sync(0xffffffffu, sendU, 16);
        float V = keepV + __shfl_xor_sync(0xffffffffu, sendV, 16);
        float za, zb;
        gelu2(U + V, U - V, za, zb);           // t0: z(p), z(1024-p); t1: z(512+p), z(512-p)
        float sP = za + zb;                    // A (t0) / B (t1)
        float sM = zb - za;                    // C (t0) / D (t1)
        float oP = __shfl_xor_sync(0xffffffffu, sP, 16);
        float oM = __shfl_xor_sync(0xffffffffu, sM, 16);
        float A = hh ? oP : sP,  B = hh ? sP : oP;
        float C = hh ? oM : sM,  D = hh ? sM : oM;
        u64 r2 = pk2(A + B, A - B);            // (rp, rm) cos weights even/odd
        u64 i2 = pk2(C + D, C - D);            // (ip, im) sin weights even/odd
        #pragma unroll
        for (int k = 0; k < 8; k++) {
            zfr2[k] = f2fma(r2, c2[k], zfr2[k]);
            zfi2[k] = f2fma(i2, s2[k], zfi2[k]);
        }
    }

    #pragma unroll
    for (int k = 0; k < 8; k++) {
        float r0, r1, i0, i1;
        un2(zfr2[k], r0, r1);
        un2(zfi2[k], i0, i1);
        int m0 = hh * 16 + 2 * k;
        g_Zf[((size_t)((m0    ) * 2 + 0) * NB + b) * HID + ch] = r0;
        g_Zf[((size_t)((m0    ) * 2 + 1) * NB + b) * HID + ch] = i0;
        g_Zf[((size_t)((m0 + 1) * 2 + 0) * NB + b) * HID + ch] = r1;
        g_Zf[((size_t)((m0 + 1) * 2 + 1) * NB + b) * HID + ch] = i1;
    }
}

// ---------------- K_mix: per-mode complex GEMM (scalar, proven R4 form) ----------------
__global__ __launch_bounds__(256, 2) void k_mix() {
    int m  = blockIdx.x;                       // mode
    int bt = blockIdx.y;                       // b-tile of 64
    __shared__ float Zr[64 * 33], Zi[64 * 33];
    __shared__ float Wr[32 * 128], Wi[32 * 128];
    int t = threadIdx.x;
    int bo_g = t >> 4, o_g = t & 15;
    int b0 = bo_g * 4, o0 = o_g * 8;

    float accr[4][8], acci[4][8];
    #pragma unroll
    for (int x = 0; x < 4; x++)
        #pragma unroll
        for (int y = 0; y < 8; y++) { accr[x][y] = 0.0f; acci[x][y] = 0.0f; }

    const float* Zsr = g_Zf + ((size_t)(m * 2 + 0) * NB + bt * 64) * HID;
    const float* Zsi = g_Zf + ((size_t)(m * 2 + 1) * NB + bt * 64) * HID;

    for (int i0 = 0; i0 < HID; i0 += 32) {
        __syncthreads();
        for (int idx = t; idx < 64 * 32; idx += 256) {
            int bb = idx >> 5, ic = idx & 31;
            Zr[bb * 33 + ic] = Zsr[bb * HID + i0 + ic];
            Zi[bb * 33 + ic] = Zsi[bb * HID + i0 + ic];
        }
        for (int idx = t; idx < 32 * 128; idx += 256) {
            int ic = idx >> 7, o = idx & 127;
            Wr[idx] = g_w2tr[((size_t)m * HID + i0 + ic) * HID + o];
            Wi[idx] = g_w2ti[((size_t)m * HID + i0 + ic) * HID + o];
        }
        __syncthreads();
        #pragma unroll 4
        for (int ic = 0; ic < 32; ic++) {
            float zr[4], zi[4];
            #pragma unroll
            for (int bb = 0; bb < 4; bb++) {
                zr[bb] = Zr[(b0 + bb) * 33 + ic];
                zi[bb] = Zi[(b0 + bb) * 33 + ic];
            }
            float wr[8], wi[8];
            #pragma unroll
            for (int q = 0; q < 2; q++) {
                float4 a = reinterpret_cast<const float4*>(&Wr[ic * 128 + o0])[q];
                float4 c = reinterpret_cast<const float4*>(&Wi[ic * 128 + o0])[q];
                wr[4*q+0]=a.x; wr[4*q+1]=a.y; wr[4*q+2]=a.z; wr[4*q+3]=a.w;
                wi[4*q+0]=c.x; wi[4*q+1]=c.y; wi[4*q+2]=c.z; wi[4*q+3]=c.w;
            }
            #pragma unroll
            for (int bb = 0; bb < 4; bb++)
                #pragma unroll
                for (int oo = 0; oo < 8; oo++) {
                    accr[bb][oo] = fmaf(zr[bb], wr[oo], fmaf(-zi[bb], wi[oo], accr[bb][oo]));
                    acci[bb][oo] = fmaf(zr[bb], wi[oo], fmaf( zi[bb], wr[oo], acci[bb][oo]));
                }
        }
    }
    #pragma unroll
    for (int bb = 0; bb < 4; bb++) {
        size_t rowr = ((size_t)(m * 2 + 0) * NB + bt * 64 + b0 + bb) * HID + o0;
        size_t rowi = ((size_t)(m * 2 + 1) * NB + bt * 64 + b0 + bb) * HID + o0;
        #pragma unroll
        for (int oo = 0; oo < 8; oo++) {
            g_of2[rowr + oo] = accr[bb][oo];
            g_of2[rowi + oo] = acci[bb][oo];
        }
    }
}

// ---------------- K_layer2: synth + gelu + mean (quad symmetry, f32x2) ----------------
__global__ __launch_bounds__(256, 2) void k_layer2(float* __restrict__ out) {
    int b = blockIdx.x;
    int t = threadIdx.x;
    int lane = t & 31, w = t >> 5, hh = lane >> 4;
    int o = w * 16 + (lane & 15);

    float br[16], bi[16];
    #pragma unroll
    for (int j = 0; j < 16; j++) {
        int m = hh * 16 + j;
        float orr = __ldg(&g_of2[((size_t)(m * 2 + 0) * NB + b) * HID + o]);
        float oii = __ldg(&g_of2[((size_t)(m * 2 + 1) * NB + b) * HID + o]);
        float km = (m == 0) ? (1.0f / SLEN) : (2.0f / SLEN);
        br[j] = km * orr;
        bi[j] = (m == 0) ? 0.0f : -km * oii;
    }

    const float4* tC = reinterpret_cast<const float4*>(g_tabC);
    const float4* tS = reinterpret_cast<const float4*>(g_tabS);
    int base = hh * 4;
    float acc = 0.0f;                          // per-thread partial (own points only)

    {   // s=0 (t0 adds) and s=512 (t1 adds)
        float c0[16], c5[16];
        #pragma unroll
        for (int q = 0; q < 4; q++) {
            float4 a = __ldg(&tC[0 * 8 + base + q]);
            float4 c = __ldg(&tC[512 * 8 + base + q]);
            c0[4*q+0]=a.x; c0[4*q+1]=a.y; c0[4*q+2]=a.z; c0[4*q+3]=a.w;
            c5[4*q+0]=c.x; c5[4*q+1]=c.y; c5[4*q+2]=c.z; c5[4*q+3]=c.w;
        }
        float u0 = 0.0f, u5 = 0.0f;
        #pragma unroll
        for (int j = 0; j < 16; j++) {
            u0 = fmaf(br[j], c0[j], u0);
            u5 = fmaf(br[j], c5[j], u5);
        }
        u0 += __shfl_xor_sync(0xffffffffu, u0, 16);
        u5 += __shfl_xor_sync(0xffffffffu, u5, 16);
        acc += gelu_fast(hh ? u5 : u0);
    }

    {   // s=256 (t0 adds) / s=768 (t1 adds)
        float c[16], sn[16];
        #pragma unroll
        for (int q = 0; q < 4; q++) {
            float4 a = __ldg(&tC[256 * 8 + base + q]);
            float4 s = __ldg(&tS[256 * 8 + base + q]);
            c [4*q+0]=a.x; c [4*q+1]=a.y; c [4*q+2]=a.z; c [4*q+3]=a.w;
            sn[4*q+0]=s.x; sn[4*q+1]=s.y; sn[4*q+2]=s.z; sn[4*q+3]=s.w;
        }
        float u = 0.0f, v = 0.0f;
        #pragma unroll
        for (int j = 0; j < 16; j++) {
            u = fmaf(br[j], c[j], u);
            v = fmaf(bi[j], sn[j], v);
        }
        float ya = u + v, yb = u - v;
        ya += __shfl_xor_sync(0xffffffffu, ya, 16);
        yb += __shfl_xor_sync(0xffffffffu, yb, 16);
        acc += gelu_fast(hh ? yb : ya);
    }

    // pack
    u64 br2[8], bi2[8];
    #pragma unroll
    for (int k = 0; k < 8; k++) {
        br2[k] = pk2(br[2*k], br[2*k+1]);
        bi2[k] = pk2(bi[2*k], bi[2*k+1]);
    }

    const double2* tC2 = reinterpret_cast<const double2*>(g_tabC);
    const double2* tS2 = reinterpret_cast<const double2*>(g_tabS);

    for (int p = 1; p <= 255; p++) {
        u64 c2[8], s2[8];
        #pragma unroll
        for (int q = 0; q < 4; q++) {
            double2 a = __ldg(&tC2[p * 8 + hh * 4 + q]);
            double2 s = __ldg(&tS2[p * 8 + hh * 4 + q]);
            c2[2*q+0] = dal(a.x); c2[2*q+1] = dal(a.y);
            s2[2*q+0] = dal(s.x); s2[2*q+1] = dal(s.y);
        }
        u64 u2 = 0ull, v2 = 0ull;
        #pragma unroll
        for (int k = 0; k < 8; k++) {
            u2 = f2fma(br2[k], c2[k], u2);
            v2 = f2fma(bi2[k], s2[k], v2);
        }
        float ue, uo, ve, vo;
        un2(u2, ue, uo); un2(v2, ve, vo);
        float Lp = ue + uo, Lm = ue - uo;
        float Mp = ve + vo, Mm = ve - vo;
        float keepU = hh ? Lm : Lp, sendU = hh ? Lp : Lm;
        float keepV = hh ? Mm : Mp, sendV = hh ? Mp : Mm;
        float U = keepU + __shfl_xor_sync(0xffffffffu, sendU, 16);
        float V = keepV + __shfl_xor_sync(0xffffffffu, sendV, 16);
        float za, zb;
        gelu2(U + V, U - V, za, zb);
        acc += za + zb;
    }

    acc += __shfl_xor_sync(0xffffffffu, acc, 16);
    if (hh == 0) out[(size_t)b * HID + o] = acc * (1.0f / SLEN);
}

// ---------------- launch ----------------
extern "C" void kernel_launch(void* const* d_in, const int* in_sizes, int n_in,
                              void* d_out, int out_size) {
    // identify inputs by size (order within a size group preserved: r then i)
    const float* hin = nullptr;
    const float* w1p[2] = {nullptr, nullptr};
    const float* w2p[2] = {nullptr, nullptr};
    int n1 = 0, n2 = 0;
    for (int i = 0; i < n_in; i++) {
        int sz = in_sizes[i];
        const float* p = (const float*)d_in[i];
        if (sz == NB * SLEN) hin = p;
        else if (sz == HID * NM) { if (n1 < 2) w1p[n1++] = p; }
        else if (sz == HID * HID * NM) { if (n2 < 2) w2p[n2++] = p; }
    }
    float* out = (float*)d_out;

    k_tab<<<(SLEN * NM + 255) / 256, 256>>>();
    k_w<<<(NM * HID * HID + 255) / 256, 256>>>(w1p[0], w1p[1], w2p[0], w2p[1]);
    k_layer1<<<NB, 256>>>(hin);
    dim3 g3(NM, 16);
    k_mix<<<g3, 256>>>();
    k_layer2<<<NB, 256>>>(out);
}

// round 8
// speedup vs baseline: 1.2781x; 1.0150x over previous
#include <cuda_runtime.h>
#include <math.h>

#define SLEN 1024
#define NM   32
#define HID  128
#define NB   1024

typedef unsigned long long u64;

// ---------------- scratch (static device memory; no allocation) ----------------
__device__ float g_tabC[SLEN*NM];          // cos(2*pi*m*s/S), [s][m]
__device__ float g_tabS[SLEN*NM];          // sin(2*pi*m*s/S), [s][m]
__device__ float g_w1tr[NM*HID];           // [m][ch]
__device__ float g_w1ti[NM*HID];
__device__ float g_w2tr[NM*HID*HID];       // [m][i][o]
__device__ float g_w2ti[NM*HID*HID];
__device__ float g_Zf [2*NM*NB*HID];       // [(m*2+ri)][b][ch]
__device__ float g_of2[2*NM*NB*HID];       // [(m*2+ri)][b][o]

// ---------------- packed f32x2 helpers ----------------
__device__ __forceinline__ u64 pk2(float lo, float hi) {
    u64 r; asm("mov.b64 %0, {%1, %2};" : "=l"(r) : "f"(lo), "f"(hi)); return r;
}
__device__ __forceinline__ void un2(u64 v, float& lo, float& hi) {
    asm("mov.b64 {%0, %1}, %2;" : "=f"(lo), "=f"(hi) : "l"(v));
}
__device__ __forceinline__ u64 f2fma(u64 a, u64 b, u64 c) {
    u64 d; asm("fma.rn.f32x2 %0, %1, %2, %3;" : "=l"(d) : "l"(a), "l"(b), "l"(c)); return d;
}
__device__ __forceinline__ u64 f2mul(u64 a, u64 b) {
    u64 d; asm("mul.rn.f32x2 %0, %1, %2;" : "=l"(d) : "l"(a), "l"(b)); return d;
}
__device__ __forceinline__ u64 f2add(u64 a, u64 b) {
    u64 d; asm("add.rn.f32x2 %0, %1, %2;" : "=l"(d) : "l"(a), "l"(b)); return d;
}
__device__ __forceinline__ u64 dal(double d) { return __double_as_longlong(d); }
#define PKC(x) pk2((x), (x))

// Fast exact-enough GELU (A&S 7.1.26 erf, max abs err 1.5e-7), scalar form.
// Used only on the 4 special points per block — keep the higher-order version.
__device__ __forceinline__ float gelu_fast(float x) {
    float q    = fabsf(x) * 0.70710678118654752f;
    float t    = __fdividef(1.0f, fmaf(0.3275911f, q, 1.0f));
    float poly = fmaf(fmaf(fmaf(fmaf(1.061405429f, t, -1.453152027f),
                               t, 1.421413741f),
                          t, -0.284496736f),
                      t, 0.254829592f) * t;
    float er   = 1.0f - poly * __expf(-q * q);
    float phi  = fmaf(copysignf(er, x), 0.5f, 0.5f);
    return x * phi;
}

// Two-point GELU, hot path: A&S 7.1.25 3-term erf (abs err 2.5e-5), packed poly.
__device__ __forceinline__ void gelu2(float xa, float xb, float& za, float& zb) {
    float qa = fabsf(xa) * 0.70710678118654752f;
    float qb = fabsf(xb) * 0.70710678118654752f;
    float ta = __fdividef(1.0f, fmaf(0.47047f, qa, 1.0f));
    float tb = __fdividef(1.0f, fmaf(0.47047f, qb, 1.0f));
    u64 t2 = pk2(ta, tb);
    u64 p  = f2fma(t2, PKC(0.7478556f), PKC(-0.0958798f));
    p = f2fma(p, t2, PKC(0.3480242f));
    p = f2mul(p, t2);
    float ea = __expf(-qa * qa), eb = __expf(-qb * qb);
    float pa, pb; un2(p, pa, pb);
    float era = fmaf(-pa, ea, 1.0f), erb = fmaf(-pb, eb, 1.0f);
    za = xa * fmaf(copysignf(era, xa), 0.5f, 0.5f);
    zb = xb * fmaf(copysignf(erb, xb), 0.5f, 0.5f);
}

// ---------------- K_tab: exact trig tables ----------------
__global__ void k_tab() {
    int idx = blockIdx.x * blockDim.x + threadIdx.x;
    if (idx >= SLEN * NM) return;
    int s = idx >> 5, m = idx & 31;
    int k = (s * m) & (SLEN - 1);              // exact phase reduction
    float x = (float)k * (1.0f / 512.0f);      // angle = pi * x = 2*pi*k/1024
    float sv, cv;
    sincospif(x, &sv, &cv);
    g_tabC[idx] = cv;
    g_tabS[idx] = sv;
}

// ---------------- K_w: weight transposes ----------------
__global__ void k_w(const float* __restrict__ w1r, const float* __restrict__ w1i,
                    const float* __restrict__ w2r, const float* __restrict__ w2i) {
    int tid = blockIdx.x * blockDim.x + threadIdx.x;
    if (tid < NM * HID) {                      // w1 src: [ch][m]
        int ch = tid >> 5, m = tid & 31;
        g_w1tr[m * HID + ch] = w1r[tid];
        g_w1ti[m * HID + ch] = w1i[tid];
    }
    if (tid < NM * HID * HID) {                // w2 src: [i][o][m]
        int m = tid & 31; int io = tid >> 5;
        int i = io >> 7;  int o = io & 127;
        g_w2tr[(m * HID + i) * HID + o] = w2r[tid];
        g_w2ti[(m * HID + i) * HID + o] = w2i[tid];
    }
}

// ---------------- K_layer1: DFT(h) -> mix w1 -> synth+gelu+analyze (fused, f32x2) -------
__global__ __launch_bounds__(256, 2) void k_layer1(const float* __restrict__ hin) {
    __shared__ float h_sm[SLEN];
    __shared__ float red[64 * 4];
    __shared__ float Hf[64];                   // [0:32) real, [32:64) imag
    int b = blockIdx.x;
    int t = threadIdx.x;

    // stage h row
    {
        const float4* src = reinterpret_cast<const float4*>(hin + (size_t)b * SLEN);
        float4* dst = reinterpret_cast<float4*>(h_sm);
        for (int j = t; j < SLEN / 4; j += 256) dst[j] = src[j];
    }
    __syncthreads();

    // forward DFT of h: Hfr[m] = sum h*cos, Hfi[m] = -sum h*sin
    {
        int out = t & 63, seg = t >> 6;
        int m = out & 31; int isI = out >> 5;
        const float* tab = isI ? g_tabS : g_tabC;
        float acc = 0.0f;
        int s0 = seg * 256;
        #pragma unroll 8
        for (int j = 0; j < 256; j++) {
            int s = s0 + j;
            acc = fmaf(h_sm[s], __ldg(&tab[s * NM + m]), acc);
        }
        red[out * 4 + seg] = acc;
    }
    __syncthreads();
    if (t < 64) {
        float v = red[t * 4] + red[t * 4 + 1] + red[t * 4 + 2] + red[t * 4 + 3];
        Hf[t] = (t >= 32) ? -v : v;
    }
    __syncthreads();

    int lane = t & 31;
    int w    = t >> 5;
    int hh   = lane >> 4;                      // mode-half / point-group owner
    int ch   = w * 16 + (lane & 15);
    float sgn  = hh ? -1.0f : 1.0f;
    float msgn = -sgn;

    // synthesis coefficients: y(s) = sum ar[m]*cos + ai[m]*sin
    float ar[16], ai[16], zfr[16], zfi[16];
    #pragma unroll
    for (int j = 0; j < 16; j++) {
        int m = hh * 16 + j;
        float hr = Hf[m], hi = Hf[32 + m];
        float a1 = __ldg(&g_w1tr[m * HID + ch]);
        float b1 = __ldg(&g_w1ti[m * HID + ch]);
        float km = (m == 0) ? (1.0f / SLEN) : (2.0f / SLEN);
        ar[j] = km * (hr * a1 - hi * b1);
        float oi = km * (hr * b1 + hi * a1);
        ai[j] = (m == 0) ? 0.0f : -oi;         // DC imag dropped by irfft
        zfr[j] = 0.0f; zfi[j] = 0.0f;
    }

    const float4* tC = reinterpret_cast<const float4*>(g_tabC);
    const float4* tS = reinterpret_cast<const float4*>(g_tabS);
    int base = hh * 4;                         // float4 offset inside 8-float4 row

    // special points s=0 and s=512 (sin == 0 there)
    {
        float c0[16], c5[16];
        #pragma unroll
        for (int q = 0; q < 4; q++) {
            float4 a = __ldg(&tC[0 * 8 + base + q]);
            float4 c = __ldg(&tC[512 * 8 + base + q]);
            c0[4*q+0]=a.x; c0[4*q+1]=a.y; c0[4*q+2]=a.z; c0[4*q+3]=a.w;
            c5[4*q+0]=c.x; c5[4*q+1]=c.y; c5[4*q+2]=c.z; c5[4*q+3]=c.w;
        }
        float u0 = 0.0f, u5 = 0.0f;
        #pragma unroll
        for (int j = 0; j < 16; j++) {
            u0 = fmaf(ar[j], c0[j], u0);
            u5 = fmaf(ar[j], c5[j], u5);
        }
        u0 += __shfl_xor_sync(0xffffffffu, u0, 16);
        u5 += __shfl_xor_sync(0xffffffffu, u5, 16);
        float z0 = gelu_fast(u0), z5 = gelu_fast(u5);
        #pragma unroll
        for (int j = 0; j < 16; j++)
            zfr[j] = fmaf(z0, c0[j], fmaf(z5, c5[j], zfr[j]));
    }

    // special pair s=256 / s=768 (half-wave symmetry)
    {
        float c[16], sn[16];
        #pragma unroll
        for (int q = 0; q < 4; q++) {
            float4 a = __ldg(&tC[256 * 8 + base + q]);
            float4 s = __ldg(&tS[256 * 8 + base + q]);
            c [4*q+0]=a.x; c [4*q+1]=a.y; c [4*q+2]=a.z; c [4*q+3]=a.w;
            sn[4*q+0]=s.x; sn[4*q+1]=s.y; sn[4*q+2]=s.z; sn[4*q+3]=s.w;
        }
        float u = 0.0f, v = 0.0f;
        #pragma unroll
        for (int j = 0; j < 16; j++) {
            u = fmaf(ar[j], c[j], u);
            v = fmaf(ai[j], sn[j], v);
        }
        float ya = u + v, yb = u - v;          // y(256), y(768)
        ya += __shfl_xor_sync(0xffffffffu, ya, 16);
        yb += __shfl_xor_sync(0xffffffffu, yb, 16);
        float ymine = hh ? yb : ya;
        float zmine = gelu_fast(ymine);
        float zoth  = __shfl_xor_sync(0xffffffffu, zmine, 16);
        float z0 = hh ? zoth : zmine;          // z(256)
        float z1 = hh ? zmine : zoth;          // z(768)
        float zp = z0 + z1, zd = z1 - z0;
        #pragma unroll
        for (int j = 0; j < 16; j++) {
            zfr[j] = fmaf(zp, c[j],  zfr[j]);
            zfi[j] = fmaf(zd, sn[j], zfi[j]);
        }
    }

    // pack coefficients and accumulators into f32x2 pairs (even/odd mode lanes)
    u64 ar2[8], ai2[8], zfr2[8], zfi2[8];
    #pragma unroll
    for (int k = 0; k < 8; k++) {
        ar2[k]  = pk2(ar[2*k],  ar[2*k+1]);
        ai2[k]  = pk2(ai[2*k],  ai[2*k+1]);
        zfr2[k] = pk2(zfr[2*k], zfr[2*k+1]);
        zfi2[k] = pk2(zfi[2*k], zfi[2*k+1]);
    }

    const double2* tC2 = reinterpret_cast<const double2*>(g_tabC);
    const double2* tS2 = reinterpret_cast<const double2*>(g_tabS);

    // quad points {p, 1024-p, 512+p, 512-p}, p = 1..255  (packed FFMA2 core)
    for (int p = 1; p <= 255; p++) {
        u64 c2[8], s2[8];
        #pragma unroll
        for (int q = 0; q < 4; q++) {
            double2 a = __ldg(&tC2[p * 8 + hh * 4 + q]);
            double2 s = __ldg(&tS2[p * 8 + hh * 4 + q]);
            c2[2*q+0] = dal(a.x); c2[2*q+1] = dal(a.y);
            s2[2*q+0] = dal(s.x); s2[2*q+1] = dal(s.y);
        }

        // split accumulation chains (2x4 deep) for latency
        u64 u2a = 0ull, u2b = 0ull, v2a = 0ull, v2b = 0ull;
        #pragma unroll
        for (int k = 0; k < 4; k++) {
            u2a = f2fma(ar2[k],     c2[k],     u2a);
            u2b = f2fma(ar2[k + 4], c2[k + 4], u2b);
            v2a = f2fma(ai2[k],     s2[k],     v2a);
            v2b = f2fma(ai2[k + 4], s2[k + 4], v2b);
        }
        float ue, uo, ve, vo;
        un2(f2add(u2a, u2b), ue, uo);
        un2(f2add(v2a, v2b), ve, vo);
        // select-free parity folds: keep = my points' combo, send = partner's
        float keepU = fmaf(sgn,  uo, ue);
        float sendU = fmaf(msgn, uo, ue);
        float keepV = fmaf(sgn,  vo, ve);
        float sendV = fmaf(msgn, vo, ve);
        float U = keepU + __shfl_xor_sync(0xffffffffu, sendU, 16);
        float V = keepV + __shfl_xor_sync(0xffffffffu, sendV, 16);
        float za, zb;
        gelu2(U + V, U - V, za, zb);           // t0: z(p), z(1024-p); t1: z(512+p), z(512-p)
        float sP = za + zb;                    // pair-sum (cos side)
        float sM = zb - za;                    // pair-diff (sin side)
        float oP = __shfl_xor_sync(0xffffffffu, sP, 16);
        float oM = __shfl_xor_sync(0xffffffffu, sM, 16);
        // cos weights: even = sP+oP, odd = sgn*(sP-oP); sin likewise
        u64 r2 = pk2(sP + oP, sgn * (sP - oP));
        u64 i2 = pk2(sM + oM, sgn * (sM - oM));
        #pragma unroll
        for (int k = 0; k < 8; k++) {
            zfr2[k] = f2fma(r2, c2[k], zfr2[k]);
            zfi2[k] = f2fma(i2, s2[k], zfi2[k]);
        }
    }

    #pragma unroll
    for (int k = 0; k < 8; k++) {
        float r0, r1, i0, i1;
        un2(zfr2[k], r0, r1);
        un2(zfi2[k], i0, i1);
        int m0 = hh * 16 + 2 * k;
        g_Zf[((size_t)((m0    ) * 2 + 0) * NB + b) * HID + ch] = r0;
        g_Zf[((size_t)((m0    ) * 2 + 1) * NB + b) * HID + ch] = i0;
        g_Zf[((size_t)((m0 + 1) * 2 + 0) * NB + b) * HID + ch] = r1;
        g_Zf[((size_t)((m0 + 1) * 2 + 1) * NB + b) * HID + ch] = i1;
    }
}

// ---------------- K_mix: per-mode complex GEMM (scalar, proven R4 form) ----------------
__global__ __launch_bounds__(256, 2) void k_mix() {
    int m  = blockIdx.x;                       // mode
    int bt = blockIdx.y;                       // b-tile of 64
    __shared__ float Zr[64 * 33], Zi[64 * 33];
    __shared__ float Wr[32 * 128], Wi[32 * 128];
    int t = threadIdx.x;
    int bo_g = t >> 4, o_g = t & 15;
    int b0 = bo_g * 4, o0 = o_g * 8;

    float accr[4][8], acci[4][8];
    #pragma unroll
    for (int x = 0; x < 4; x++)
        #pragma unroll
        for (int y = 0; y < 8; y++) { accr[x][y] = 0.0f; acci[x][y] = 0.0f; }

    const float* Zsr = g_Zf + ((size_t)(m * 2 + 0) * NB + bt * 64) * HID;
    const float* Zsi = g_Zf + ((size_t)(m * 2 + 1) * NB + bt * 64) * HID;

    for (int i0 = 0; i0 < HID; i0 += 32) {
        __syncthreads();
        for (int idx = t; idx < 64 * 32; idx += 256) {
            int bb = idx >> 5, ic = idx & 31;
            Zr[bb * 33 + ic] = Zsr[bb * HID + i0 + ic];
            Zi[bb * 33 + ic] = Zsi[bb * HID + i0 + ic];
        }
        for (int idx = t; idx < 32 * 128; idx += 256) {
            int ic = idx >> 7, o = idx & 127;
            Wr[idx] = g_w2tr[((size_t)m * HID + i0 + ic) * HID + o];
            Wi[idx] = g_w2ti[((size_t)m * HID + i0 + ic) * HID + o];
        }
        __syncthreads();
        #pragma unroll 4
        for (int ic = 0; ic < 32; ic++) {
            float zr[4], zi[4];
            #pragma unroll
            for (int bb = 0; bb < 4; bb++) {
                zr[bb] = Zr[(b0 + bb) * 33 + ic];
                zi[bb] = Zi[(b0 + bb) * 33 + ic];
            }
            float wr[8], wi[8];
            #pragma unroll
            for (int q = 0; q < 2; q++) {
                float4 a = reinterpret_cast<const float4*>(&Wr[ic * 128 + o0])[q];
                float4 c = reinterpret_cast<const float4*>(&Wi[ic * 128 + o0])[q];
                wr[4*q+0]=a.x; wr[4*q+1]=a.y; wr[4*q+2]=a.z; wr[4*q+3]=a.w;
                wi[4*q+0]=c.x; wi[4*q+1]=c.y; wi[4*q+2]=c.z; wi[4*q+3]=c.w;
            }
            #pragma unroll
            for (int bb = 0; bb < 4; bb++)
                #pragma unroll
                for (int oo = 0; oo < 8; oo++) {
                    accr[bb][oo] = fmaf(zr[bb], wr[oo], fmaf(-zi[bb], wi[oo], accr[bb][oo]));
                    acci[bb][oo] = fmaf(zr[bb], wi[oo], fmaf( zi[bb], wr[oo], acci[bb][oo]));
                }
        }
    }
    #pragma unroll
    for (int bb = 0; bb < 4; bb++) {
        size_t rowr = ((size_t)(m * 2 + 0) * NB + bt * 64 + b0 + bb) * HID + o0;
        size_t rowi = ((size_t)(m * 2 + 1) * NB + bt * 64 + b0 + bb) * HID + o0;
        #pragma unroll
        for (int oo = 0; oo < 8; oo++) {
            g_of2[rowr + oo] = accr[bb][oo];
            g_of2[rowi + oo] = acci[bb][oo];
        }
    }
}

// ---------------- K_layer2: synth + gelu + mean (quad symmetry, f32x2) ----------------
__global__ __launch_bounds__(256, 2) void k_layer2(float* __restrict__ out) {
    int b = blockIdx.x;
    int t = threadIdx.x;
    int lane = t & 31, w = t >> 5, hh = lane >> 4;
    int o = w * 16 + (lane & 15);
    float sgn  = hh ? -1.0f : 1.0f;
    float msgn = -sgn;

    float br[16], bi[16];
    #pragma unroll
    for (int j = 0; j < 16; j++) {
        int m = hh * 16 + j;
        float orr = __ldg(&g_of2[((size_t)(m * 2 + 0) * NB + b) * HID + o]);
        float oii = __ldg(&g_of2[((size_t)(m * 2 + 1) * NB + b) * HID + o]);
        float km = (m == 0) ? (1.0f / SLEN) : (2.0f / SLEN);
        br[j] = km * orr;
        bi[j] = (m == 0) ? 0.0f : -km * oii;
    }

    const float4* tC = reinterpret_cast<const float4*>(g_tabC);
    const float4* tS = reinterpret_cast<const float4*>(g_tabS);
    int base = hh * 4;
    float acc = 0.0f;                          // per-thread partial (own points only)

    {   // s=0 (t0 adds) and s=512 (t1 adds)
        float c0[16], c5[16];
        #pragma unroll
        for (int q = 0; q < 4; q++) {
            float4 a = __ldg(&tC[0 * 8 + base + q]);
            float4 c = __ldg(&tC[512 * 8 + base + q]);
            c0[4*q+0]=a.x; c0[4*q+1]=a.y; c0[4*q+2]=a.z; c0[4*q+3]=a.w;
            c5[4*q+0]=c.x; c5[4*q+1]=c.y; c5[4*q+2]=c.z; c5[4*q+3]=c.w;
        }
        float u0 = 0.0f, u5 = 0.0f;
        #pragma unroll
        for (int j = 0; j < 16; j++) {
            u0 = fmaf(br[j], c0[j], u0);
            u5 = fmaf(br[j], c5[j], u5);
        }
        u0 += __shfl_xor_sync(0xffffffffu, u0, 16);
        u5 += __shfl_xor_sync(0xffffffffu, u5, 16);
        acc += gelu_fast(hh ? u5 : u0);
    }

    {   // s=256 (t0 adds) / s=768 (t1 adds)
        float c[16], sn[16];
        #pragma unroll
        for (int q = 0; q < 4; q++) {
            float4 a = __ldg(&tC[256 * 8 + base + q]);
            float4 s = __ldg(&tS[256 * 8 + base + q]);
            c [4*q+0]=a.x; c [4*q+1]=a.y; c [4*q+2]=a.z; c [4*q+3]=a.w;
            sn[4*q+0]=s.x; sn[4*q+1]=s.y; sn[4*q+2]=s.z; sn[4*q+3]=s.w;
        }
        float u = 0.0f, v = 0.0f;
        #pragma unroll
        for (int j = 0; j < 16; j++) {
            u = fmaf(br[j], c[j], u);
            v = fmaf(bi[j], sn[j], v);
        }
        float ya = u + v, yb = u - v;
        ya += __shfl_xor_sync(0xffffffffu, ya, 16);
        yb += __shfl_xor_sync(0xffffffffu, yb, 16);
        acc += gelu_fast(hh ? yb : ya);
    }

    // pack
    u64 br2[8], bi2[8];
    #pragma unroll
    for (int k = 0; k < 8; k++) {
        br2[k] = pk2(br[2*k], br[2*k+1]);
        bi2[k] = pk2(bi[2*k], bi[2*k+1]);
    }

    const double2* tC2 = reinterpret_cast<const double2*>(g_tabC);
    const double2* tS2 = reinterpret_cast<const double2*>(g_tabS);

    for (int p = 1; p <= 255; p++) {
        u64 c2[8], s2[8];
        #pragma unroll
        for (int q = 0; q < 4; q++) {
            double2 a = __ldg(&tC2[p * 8 + hh * 4 + q]);
            double2 s = __ldg(&tS2[p * 8 + hh * 4 + q]);
            c2[2*q+0] = dal(a.x); c2[2*q+1] = dal(a.y);
            s2[2*q+0] = dal(s.x); s2[2*q+1] = dal(s.y);
        }
        u64 u2a = 0ull, u2b = 0ull, v2a = 0ull, v2b = 0ull;
        #pragma unroll
        for (int k = 0; k < 4; k++) {
            u2a = f2fma(br2[k],     c2[k],     u2a);
            u2b = f2fma(br2[k + 4], c2[k + 4], u2b);
            v2a = f2fma(bi2[k],     s2[k],     v2a);
            v2b = f2fma(bi2[k + 4], s2[k + 4], v2b);
        }
        float ue, uo, ve, vo;
        un2(f2add(u2a, u2b), ue, uo);
        un2(f2add(v2a, v2b), ve, vo);
        float keepU = fmaf(sgn,  uo, ue);
        float sendU = fmaf(msgn, uo, ue);
        float keepV = fmaf(sgn,  vo, ve);
        float sendV = fmaf(msgn, vo, ve);
        float U = keepU + __shfl_xor_sync(0xffffffffu, sendU, 16);
        float V = keepV + __shfl_xor_sync(0xffffffffu, sendV, 16);
        float za, zb;
        gelu2(U + V, U - V, za, zb);
        acc += za + zb;
    }

    acc += __shfl_xor_sync(0xffffffffu, acc, 16);
    if (hh == 0) out[(size_t)b * HID + o] = acc * (1.0f / SLEN);
}

// ---------------- launch ----------------
extern "C" void kernel_launch(void* const* d_in, const int* in_sizes, int n_in,
                              void* d_out, int out_size) {
    // identify inputs by size (order within a size group preserved: r then i)
    const float* hin = nullptr;
    const float* w1p[2] = {nullptr, nullptr};
    const float* w2p[2] = {nullptr, nullptr};
    int n1 = 0, n2 = 0;
    for (int i = 0; i < n_in; i++) {
        int sz = in_sizes[i];
        const float* p = (const float*)d_in[i];
        if (sz == NB * SLEN) hin = p;
        else if (sz == HID * NM) { if (n1 < 2) w1p[n1++] = p; }
        else if (sz == HID * HID * NM) { if (n2 < 2) w2p[n2++] = p; }
    }
    float* out = (float*)d_out;

    k_tab<<<(SLEN * NM + 255) / 256, 256>>>();
    k_w<<<(NM * HID * HID + 255) / 256, 256>>>(w1p[0], w1p[1], w2p[0], w2p[1]);
    k_layer1<<<NB, 256>>>(hin);
    dim3 g3(NM, 16);
    k_mix<<<g3, 256>>>();
    k_layer2<<<NB, 256>>>(out);
}